// round 2
// baseline (speedup 1.0000x reference)
#include <cuda_runtime.h>
#include <cstdint>

#define N 4096
#define D 128
#define CAND_CAP (1u << 22)

// ---------------- device globals (scratch; no allocations allowed) ----------------
__device__ __align__(16) float g_en[N * D];       // normalized embeddings
__device__ unsigned g_hist1[4096];
__device__ unsigned g_zeroPairs;
__device__ unsigned g_prefix1;     // selected top-12 bits
__device__ unsigned g_rankRem;     // remaining pair-rank within selected bin
__device__ unsigned g_mLo, g_mHi;  // pair ranks for interpolation
__device__ float    g_frac;        // interpolation fraction (replicates jax fp32 math)
__device__ unsigned g_candCount;
__device__ unsigned g_minAboveBin;
__device__ unsigned g_cand[CAND_CAP];
__device__ float    g_actThresh;
__device__ unsigned char g_low[N];
__device__ unsigned g_rowMinPos[N];  // encoded min-dot over positive mask (per anchor)
__device__ unsigned g_rowMaxNeg[N];  // encoded max-dot over negative mask (per anchor)

// order-preserving float <-> uint encode
__device__ __forceinline__ unsigned encodeF(float f) {
    unsigned u = __float_as_uint(f);
    return (u & 0x80000000u) ? ~u : (u | 0x80000000u);
}
__device__ __forceinline__ float decodeF(unsigned u) {
    return (u & 0x80000000u) ? __uint_as_float(u & 0x7FFFFFFFu)
                             : __uint_as_float(~u);
}

// ---------------- K1: fused init + normalize + sort(median) ----------------
__global__ void prepK(const float* __restrict__ emb, const float* __restrict__ au) {
    __shared__ float s[N];
    __shared__ float thSh;
    int tid = threadIdx.x;  // 1024
    if (blockIdx.x < 128) {
        int warp = blockIdx.x * 32 + (tid >> 5);
        int lane = tid & 31;
        const float4* p = (const float4*)(emb + (size_t)warp * D);
        float4 v = p[lane];
        float ss = v.x * v.x + v.y * v.y + v.z * v.z + v.w * v.w;
#pragma unroll
        for (int st = 16; st > 0; st >>= 1) ss += __shfl_xor_sync(0xffffffffu, ss, st);
        float inv = 1.0f / fmaxf(sqrtf(ss), 1e-12f);
        float4 o;
        o.x = v.x * inv; o.y = v.y * inv; o.z = v.z * inv; o.w = v.w * inv;
        ((float4*)(g_en + (size_t)warp * D))[lane] = o;
        return;
    }
    // block 128: init accumulators + bitonic sort for median
    for (int x = tid; x < 4096; x += 1024) {
        g_hist1[x] = 0u;
        g_rowMinPos[x] = 0xFFFFFFFFu;
        g_rowMaxNeg[x] = 0u;
    }
    if (tid == 0) {
        g_zeroPairs = 0u;
        g_candCount = 0u;
        g_minAboveBin = 0xFFFFFFFFu;
        g_rankRem = 0u;
    }
    for (int i = tid; i < N; i += 1024) s[i] = au[i];
    __syncthreads();
    for (int k = 2; k <= N; k <<= 1) {
        for (int j = k >> 1; j > 0; j >>= 1) {
            for (int idx = tid; idx < N; idx += 1024) {
                int p = idx ^ j;
                if (p > idx) {
                    float a = s[idx], b = s[p];
                    bool up = ((idx & k) == 0);
                    bool sw = up ? (a > b) : (a < b);
                    if (sw) { s[idx] = b; s[p] = a; }
                }
            }
            __syncthreads();
        }
    }
    if (tid == 0) {
        float th = 0.5f * s[2047] + 0.5f * s[2048];
        thSh = th;
    }
    __syncthreads();
    float th = thSh;
    for (int i = tid; i < N; i += 1024) g_low[i] = (au[i] < th) ? 1 : 0;
}

// ---------------- K2: 12-bit histogram over unordered pairs (j > i) ----------------
__global__ void hist1K(const float* __restrict__ t) {
    __shared__ float ts[N];
    __shared__ unsigned hist[4096];
    __shared__ unsigned sZero;
    int tid = threadIdx.x;  // 256
    for (int i = tid; i < N; i += 256) ts[i] = t[i];
    for (int i = tid; i < 4096; i += 256) hist[i] = 0u;
    if (tid == 0) sZero = 0u;
    __syncthreads();
    unsigned zc = 0u;
    for (int i = blockIdx.x; i < N; i += gridDim.x) {
        float ti = ts[i];
        for (int j = i + 1 + tid; j < N; j += 256) {
            unsigned b = __float_as_uint(fabsf(ti - ts[j]));
            if (b == 0u) { zc++; continue; }
            atomicAdd(&hist[b >> 20], 1u);
        }
    }
    __syncthreads();
    for (int i = tid; i < 4096; i += 256)
        if (hist[i]) atomicAdd(&g_hist1[i], hist[i]);
    if (zc) atomicAdd(&sZero, zc);
    __syncthreads();
    if (tid == 0 && sZero) atomicAdd(&g_zeroPairs, sZero);
}

// ---------------- K3: scan 4096-bin hist, find bin holding the quantile rank ----------------
__global__ void scan1K() {
    __shared__ unsigned warpS[32];
    __shared__ unsigned rankSh;
    int tid = threadIdx.x;  // 1024
    int lane = tid & 31, wid = tid >> 5;
    if (tid == 0) {
        unsigned long long n = 16773120ull - 2ull * (unsigned long long)g_zeroPairs;
        float nf = (float)(n - 1ull);          // (n-1).astype(float32)
        float pos = 0.2f * nf;                 // q * (n-1)  [fp32!]
        float lof = floorf(pos);
        g_frac = pos - lof;
        unsigned lo = (unsigned)lof;
        g_mLo = lo >> 1;                       // flat rank -> pair rank
        g_mHi = (lo + 1u) >> 1;
        rankSh = g_mLo;
    }
    __syncthreads();
    unsigned rank = rankSh;
    unsigned h0 = g_hist1[tid * 4 + 0], h1 = g_hist1[tid * 4 + 1];
    unsigned h2 = g_hist1[tid * 4 + 2], h3 = g_hist1[tid * 4 + 3];
    unsigned lsum = h0 + h1 + h2 + h3;
    unsigned v = lsum;
#pragma unroll
    for (int s = 1; s < 32; s <<= 1) {
        unsigned o = __shfl_up_sync(0xffffffffu, v, s);
        if (lane >= s) v += o;
    }
    if (lane == 31) warpS[wid] = v;
    __syncthreads();
    if (wid == 0) {
        unsigned w = warpS[lane];
#pragma unroll
        for (int s = 1; s < 32; s <<= 1) {
            unsigned o = __shfl_up_sync(0xffffffffu, w, s);
            if (lane >= s) w += o;
        }
        warpS[lane] = w;
    }
    __syncthreads();
    unsigned base = (v - lsum) + (wid ? warpS[wid - 1] : 0u);
    unsigned cum = base;
    unsigned hs[4] = {h0, h1, h2, h3};
#pragma unroll
    for (int c = 0; c < 4; c++) {
        unsigned h = hs[c];
        if (h && rank >= cum && rank < cum + h) {
            g_prefix1 = (unsigned)(tid * 4 + c);
            g_rankRem = rank - cum;
        }
        cum += h;
    }
}

// ---------------- K4: collect candidates in selected bin + min above bin ----------------
__global__ void collectK(const float* __restrict__ t) {
    __shared__ float ts[N];
    __shared__ unsigned sMin;
    int tid = threadIdx.x;  // 256
    int lane = tid & 31;
    for (int i = tid; i < N; i += 256) ts[i] = t[i];
    if (tid == 0) sMin = 0xFFFFFFFFu;
    unsigned p1 = g_prefix1;
    __syncthreads();
    unsigned myMin = 0xFFFFFFFFu;
    for (int i = blockIdx.x; i < N; i += gridDim.x) {
        float ti = ts[i];
        for (int j0 = i + 1; j0 < N; j0 += 256) {
            int j = j0 + tid;
            bool valid = j < N;
            float tj = valid ? ts[j] : ti;
            unsigned b = __float_as_uint(fabsf(ti - tj));
            bool nz = valid && (b != 0u);
            unsigned bin = b >> 20;
            bool match = nz && (bin == p1);
            unsigned m = __ballot_sync(0xffffffffu, match);
            if (m) {
                int leader = __ffs(m) - 1;
                unsigned base = 0u;
                if (lane == leader) base = atomicAdd(&g_candCount, (unsigned)__popc(m));
                base = __shfl_sync(0xffffffffu, base, leader);
                if (match) {
                    unsigned idx = base + (unsigned)__popc(m & ((1u << lane) - 1u));
                    if (idx < CAND_CAP) g_cand[idx] = b;
                }
            }
            if (nz && bin > p1) myMin = min(myMin, b);
        }
    }
#pragma unroll
    for (int s = 16; s > 0; s >>= 1)
        myMin = min(myMin, __shfl_xor_sync(0xffffffffu, myMin, s));
    if (lane == 0) atomicMin(&sMin, myMin);
    __syncthreads();
    if (tid == 0 && sMin != 0xFFFFFFFFu) atomicMin(&g_minAboveBin, sMin);
}

// ---------------- K5: finish radix select over candidates, compute act threshold ----------------
__global__ void candFinalK() {
    __shared__ unsigned hist[4096];
    __shared__ unsigned warpS[32];
    __shared__ unsigned shA, shB, shC;
    __shared__ unsigned shMinHi;
    int tid = threadIdx.x;  // 1024
    int lane = tid & 31, wid = tid >> 5;
    unsigned cc = g_candCount;
    if (cc > CAND_CAP) cc = CAND_CAP;
    for (int i = tid; i < 4096; i += 1024) hist[i] = 0u;
    if (tid == 0) shMinHi = g_minAboveBin;
    __syncthreads();
    // pass A: 12-bit hist on bits[19:8]
    for (unsigned i = tid; i < cc; i += 1024) atomicAdd(&hist[(g_cand[i] >> 8) & 0xFFFu], 1u);
    __syncthreads();
    {   // block-parallel select on hist[4096]
        unsigned rank = g_rankRem;
        unsigned h0 = hist[tid * 4 + 0], h1 = hist[tid * 4 + 1];
        unsigned h2 = hist[tid * 4 + 2], h3 = hist[tid * 4 + 3];
        unsigned lsum = h0 + h1 + h2 + h3;
        unsigned v = lsum;
#pragma unroll
        for (int s = 1; s < 32; s <<= 1) {
            unsigned o = __shfl_up_sync(0xffffffffu, v, s);
            if (lane >= s) v += o;
        }
        if (lane == 31) warpS[wid] = v;
        __syncthreads();
        if (wid == 0) {
            unsigned w = warpS[lane];
#pragma unroll
            for (int s = 1; s < 32; s <<= 1) {
                unsigned o = __shfl_up_sync(0xffffffffu, w, s);
                if (lane >= s) w += o;
            }
            warpS[lane] = w;
        }
        __syncthreads();
        unsigned base = (v - lsum) + (wid ? warpS[wid - 1] : 0u);
        unsigned cum = base;
        unsigned hs[4] = {h0, h1, h2, h3};
#pragma unroll
        for (int c = 0; c < 4; c++) {
            unsigned h = hs[c];
            if (h && rank >= cum && rank < cum + h) {
                shA = (unsigned)(tid * 4 + c);  // 12-bit mid prefix
                shB = rank - cum;               // rank within 24-bit bin
            }
            cum += h;
        }
    }
    __syncthreads();
    unsigned p2 = shA, rank2 = shB;
    // pass B: 8-bit hist on bits[7:0] within 24-bit prefix
    if (tid < 256) hist[tid] = 0u;
    __syncthreads();
    for (unsigned i = tid; i < cc; i += 1024) {
        unsigned b = g_cand[i];
        if (((b >> 8) & 0xFFFu) == p2) atomicAdd(&hist[b & 0xFFu], 1u);
    }
    __syncthreads();
    if (tid == 0) {
        unsigned rank = rank2, cum = 0u, vlo = 0u, binCnt = 0u, rem = 0u;
        unsigned p1 = g_prefix1;
        for (int x = 0; x < 256; x++) {
            unsigned h = hist[x];
            if (h && rank >= cum && rank < cum + h) {
                vlo = (p1 << 20) | (p2 << 8) | (unsigned)x;
                binCnt = h;
                rem = rank - cum;
            }
            cum += h;
        }
        shA = vlo; shB = rem; shC = binCnt;
    }
    __syncthreads();
    unsigned vlo = shA, rem3 = shB, binCnt = shC;
    // pass C: min candidate strictly above vlo
    unsigned myMin = 0xFFFFFFFFu;
    for (unsigned i = tid; i < cc; i += 1024) {
        unsigned b = g_cand[i];
        if (b > vlo) myMin = min(myMin, b);
    }
#pragma unroll
    for (int s = 16; s > 0; s >>= 1)
        myMin = min(myMin, __shfl_xor_sync(0xffffffffu, myMin, s));
    if (lane == 0) atomicMin(&shMinHi, myMin);
    __syncthreads();
    if (tid == 0) {
        float flo = __uint_as_float(vlo);
        float fhi;
        if (g_mHi == g_mLo) fhi = flo;
        else if (rem3 + 1u < binCnt) fhi = flo;   // duplicate of vlo
        else fhi = __uint_as_float(shMinHi);
        float f = g_frac;
        g_actThresh = __fadd_rn(__fmul_rn(flo, 1.0f - f), __fmul_rn(fhi, f));
    }
}

// ---------------- K6: symmetric fp32x2 GEMM + fused masked row/col reductions ----------------
__global__ __launch_bounds__(256, 1) void gemmMaskK(const float* __restrict__ t) {
    __shared__ __align__(16) float2 As2[16][128];
    __shared__ __align__(16) float2 Bs2[16][128];
    __shared__ unsigned sColMin[8][128];
    __shared__ unsigned sColMax[8][128];

    int tid = threadIdx.x;
    // triangular block mapping: bi <= bj over 32x32 tiles (528 blocks)
    int b = blockIdx.x;
    int bi = 0;
    while (b >= 32 - bi) { b -= 32 - bi; bi++; }
    int bj = bi + b;
    int ri = bi * 128, rj = bj * 128;

    int r0 = (tid >> 4) * 4;
    int c0 = (tid & 15) * 4;

    unsigned long long acc[8][8];
#pragma unroll
    for (int r = 0; r < 8; r++)
#pragma unroll
        for (int c = 0; c < 8; c++) acc[r][c] = 0ull;

    int lr = tid >> 1, lh = tid & 1;
    for (int kc = 0; kc < 4; kc++) {
        const float4* pa = (const float4*)(g_en + (size_t)(ri + lr) * D + kc * 32 + lh * 16);
        const float4* pb = (const float4*)(g_en + (size_t)(rj + lr) * D + kc * 32 + lh * 16);
        float4 a0 = pa[0], a1 = pa[1], a2 = pa[2], a3 = pa[3];
        float4 b0 = pb[0], b1 = pb[1], b2 = pb[2], b3 = pb[3];
        if (kc) __syncthreads();
        int kb = lh * 8;
        As2[kb + 0][lr] = make_float2(a0.x, a0.y);
        As2[kb + 1][lr] = make_float2(a0.z, a0.w);
        As2[kb + 2][lr] = make_float2(a1.x, a1.y);
        As2[kb + 3][lr] = make_float2(a1.z, a1.w);
        As2[kb + 4][lr] = make_float2(a2.x, a2.y);
        As2[kb + 5][lr] = make_float2(a2.z, a2.w);
        As2[kb + 6][lr] = make_float2(a3.x, a3.y);
        As2[kb + 7][lr] = make_float2(a3.z, a3.w);
        Bs2[kb + 0][lr] = make_float2(b0.x, b0.y);
        Bs2[kb + 1][lr] = make_float2(b0.z, b0.w);
        Bs2[kb + 2][lr] = make_float2(b1.x, b1.y);
        Bs2[kb + 3][lr] = make_float2(b1.z, b1.w);
        Bs2[kb + 4][lr] = make_float2(b2.x, b2.y);
        Bs2[kb + 5][lr] = make_float2(b2.z, b2.w);
        Bs2[kb + 6][lr] = make_float2(b3.x, b3.y);
        Bs2[kb + 7][lr] = make_float2(b3.z, b3.w);
        __syncthreads();
#pragma unroll
        for (int k2 = 0; k2 < 16; k2++) {
            ulonglong2 A0 = *(const ulonglong2*)&As2[k2][r0];
            ulonglong2 A1 = *(const ulonglong2*)&As2[k2][r0 + 2];
            ulonglong2 A2 = *(const ulonglong2*)&As2[k2][64 + r0];
            ulonglong2 A3 = *(const ulonglong2*)&As2[k2][64 + r0 + 2];
            ulonglong2 B0 = *(const ulonglong2*)&Bs2[k2][c0];
            ulonglong2 B1 = *(const ulonglong2*)&Bs2[k2][c0 + 2];
            ulonglong2 B2 = *(const ulonglong2*)&Bs2[k2][64 + c0];
            ulonglong2 B3 = *(const ulonglong2*)&Bs2[k2][64 + c0 + 2];
            unsigned long long av[8] = {A0.x, A0.y, A1.x, A1.y, A2.x, A2.y, A3.x, A3.y};
            unsigned long long bv[8] = {B0.x, B0.y, B1.x, B1.y, B2.x, B2.y, B3.x, B3.y};
#pragma unroll
            for (int r = 0; r < 8; r++)
#pragma unroll
                for (int c = 0; c < 8; c++)
                    asm("fma.rn.f32x2 %0, %1, %2, %0;"
                        : "+l"(acc[r][c]) : "l"(av[r]), "l"(bv[c]));
        }
    }

    // unpack packed partial sums
    float dot[8][8];
#pragma unroll
    for (int r = 0; r < 8; r++)
#pragma unroll
        for (int c = 0; c < 8; c++) {
            float lo = __uint_as_float((unsigned)(acc[r][c] & 0xFFFFFFFFull));
            float hi = __uint_as_float((unsigned)(acc[r][c] >> 32));
            dot[r][c] = lo + hi;
        }

    // ---- fused epilogue: masked min/max for BOTH row anchors and col anchors ----
    int rows[8], cols[8];
#pragma unroll
    for (int u = 0; u < 4; u++) {
        rows[u] = ri + r0 + u;
        rows[4 + u] = ri + 64 + r0 + u;
        cols[u] = rj + c0 + u;
        cols[4 + u] = rj + 64 + c0 + u;
    }
    float ti[8], tj[8];
    int li[8], lj[8];
#pragma unroll
    for (int u = 0; u < 8; u++) {
        ti[u] = t[rows[u]];
        tj[u] = t[cols[u]];
        li[u] = g_low[rows[u]];
        lj[u] = g_low[cols[u]];
    }
    float actT = g_actThresh;
    float pMin[8], nMax[8], cMin[8], cMax[8];
#pragma unroll
    for (int u = 0; u < 8; u++) {
        pMin[u] = 3.402823466e38f; nMax[u] = -3.402823466e38f;
        cMin[u] = 3.402823466e38f; cMax[u] = -3.402823466e38f;
    }
#pragma unroll
    for (int r = 0; r < 8; r++) {
#pragma unroll
        for (int c = 0; c < 8; c++) {
            float ad = fabsf(ti[r] - tj[c]);
            if (ad < actT) {
                float dv = dot[r][c];
                bool neq = rows[r] != cols[c];
                // anchor = row i, candidate = col j
                if (lj[c]) { if (neq) pMin[r] = fminf(pMin[r], dv); }
                else nMax[r] = fmaxf(nMax[r], dv);
                // anchor = col j, candidate = row i (transpose block)
                if (li[r]) { if (neq) cMin[c] = fminf(cMin[c], dv); }
                else cMax[c] = fmaxf(cMax[c], dv);
            }
        }
    }
    // row side: reduce across 16-lane groups sharing the same rows
#pragma unroll
    for (int s = 8; s > 0; s >>= 1) {
#pragma unroll
        for (int r = 0; r < 8; r++) {
            pMin[r] = fminf(pMin[r], __shfl_down_sync(0xffffffffu, pMin[r], s, 16));
            nMax[r] = fmaxf(nMax[r], __shfl_down_sync(0xffffffffu, nMax[r], s, 16));
        }
    }
    if ((tid & 15) == 0) {
#pragma unroll
        for (int r = 0; r < 8; r++) {
            if (pMin[r] < 3.0e38f) atomicMin(&g_rowMinPos[rows[r]], encodeF(pMin[r]));
            if (nMax[r] > -3.0e38f) atomicMax(&g_rowMaxNeg[rows[r]], encodeF(nMax[r]));
        }
    }
    // col side: combine lane pairs (l, l^16), stage per-warp partials, then flush
    unsigned eMin[8], eMax[8];
#pragma unroll
    for (int u = 0; u < 8; u++) {
        eMin[u] = encodeF(cMin[u]);
        eMax[u] = encodeF(cMax[u]);
        eMin[u] = min(eMin[u], __shfl_xor_sync(0xffffffffu, eMin[u], 16));
        eMax[u] = max(eMax[u], __shfl_xor_sync(0xffffffffu, eMax[u], 16));
    }
    int wrp = tid >> 5;
    if ((tid & 31) < 16) {
#pragma unroll
        for (int u = 0; u < 4; u++) {
            sColMin[wrp][c0 + u] = eMin[u];
            sColMin[wrp][64 + c0 + u] = eMin[4 + u];
            sColMax[wrp][c0 + u] = eMax[u];
            sColMax[wrp][64 + c0 + u] = eMax[4 + u];
        }
    }
    __syncthreads();
    if (tid < 128) {
        unsigned v = sColMin[0][tid];
#pragma unroll
        for (int w = 1; w < 8; w++) v = min(v, sColMin[w][tid]);
        if (v < 0xFF000000u) atomicMin(&g_rowMinPos[rj + tid], v);
    } else {
        int c = tid - 128;
        unsigned v = sColMax[0][c];
#pragma unroll
        for (int w = 1; w < 8; w++) v = max(v, sColMax[w][c]);
        if (v > 0x01000000u) atomicMax(&g_rowMaxNeg[rj + c], v);
    }
}

// ---------------- K7: per-anchor loss + mean ----------------
__global__ void finalK(float* __restrict__ out, int out_size) {
    __shared__ float sSum[32];
    __shared__ unsigned sCnt[32];
    int tid = threadIdx.x;  // 1024
    int lane = tid & 31, wid = tid >> 5;
    float sum = 0.0f;
    unsigned cnt = 0u;
    for (int i = tid; i < N; i += 1024) {
        if (!g_low[i]) continue;
        unsigned ep = g_rowMinPos[i];
        if (ep == 0xFFFFFFFFu) continue;  // no positive
        unsigned en = g_rowMaxNeg[i];
        if (en == 0u) continue;           // no negative
        float minDot = decodeF(ep);
        float maxDot = decodeF(en);
        float hp = sqrtf(fmaxf(2.0f - 2.0f * minDot, 1e-12f));
        float hn = sqrtf(fmaxf(2.0f - 2.0f * maxDot, 1e-12f));
        float tl = hp - hn + 0.5f;
        if (tl < 0.0f) tl = 0.0f;
        sum += tl;
        cnt++;
    }
#pragma unroll
    for (int s = 16; s > 0; s >>= 1) {
        sum += __shfl_down_sync(0xffffffffu, sum, s);
        cnt += __shfl_down_sync(0xffffffffu, cnt, s);
    }
    if (lane == 0) { sSum[wid] = sum; sCnt[wid] = cnt; }
    __syncthreads();
    if (wid == 0) {
        float s2 = sSum[lane];
        unsigned c2 = sCnt[lane];
#pragma unroll
        for (int s = 16; s > 0; s >>= 1) {
            s2 += __shfl_down_sync(0xffffffffu, s2, s);
            c2 += __shfl_down_sync(0xffffffffu, c2, s);
        }
        if (lane == 0) out[0] = s2 / (float)(c2 > 0u ? c2 : 1u);
    }
    for (int i = tid; i < out_size; i += 1024)
        if (i > 0) out[i] = 0.0f;
}

// ---------------- launch ----------------
extern "C" void kernel_launch(void* const* d_in, const int* in_sizes, int n_in,
                              void* d_out, int out_size) {
    const float* emb = (const float*)d_in[0];
    const float* tg = (const float*)d_in[1];
    const float* au = (const float*)d_in[2];
    float* out = (float*)d_out;

    prepK<<<129, 1024>>>(emb, au);
    hist1K<<<512, 256>>>(tg);
    scan1K<<<1, 1024>>>();
    collectK<<<512, 256>>>(tg);
    candFinalK<<<1, 1024>>>();
    gemmMaskK<<<528, 256>>>(tg);
    finalK<<<1, 1024>>>(out, out_size);
}

// round 3
// speedup vs baseline: 1.0779x; 1.0779x over previous
#include <cuda_runtime.h>
#include <cstdint>

#define N 4096
#define D 128

// ---------------- device globals (scratch; no allocations allowed) ----------------
__device__ __align__(16) float g_en[N * D];   // normalized embeddings
__device__ float g_tsorted[N];                // sorted targets
__device__ unsigned g_vloBits, g_vhiBits;     // selected order-statistic bit patterns
__device__ float    g_frac;                   // interpolation fraction (fp32, jax-exact)
__device__ unsigned char g_low[N];
__device__ unsigned g_rowMinPos[N];  // encoded min-dot over positive mask (per anchor)
__device__ unsigned g_rowMaxNeg[N];  // encoded max-dot over negative mask (per anchor)

// order-preserving float <-> uint encode
__device__ __forceinline__ unsigned encodeF(float f) {
    unsigned u = __float_as_uint(f);
    return (u & 0x80000000u) ? ~u : (u | 0x80000000u);
}
__device__ __forceinline__ float decodeF(unsigned u) {
    return (u & 0x80000000u) ? __uint_as_float(u & 0x7FFFFFFFu)
                             : __uint_as_float(~u);
}

// bitonic sort of s[N] in shared memory, 1024 threads
__device__ void bitonicSort(float* s) {
    int tid = threadIdx.x;
    for (int k = 2; k <= N; k <<= 1) {
        for (int j = k >> 1; j > 0; j >>= 1) {
            for (int idx = tid; idx < N; idx += 1024) {
                int p = idx ^ j;
                if (p > idx) {
                    float a = s[idx], b = s[p];
                    bool up = ((idx & k) == 0);
                    bool sw = up ? (a > b) : (a < b);
                    if (sw) { s[idx] = b; s[p] = a; }
                }
            }
            __syncthreads();
        }
    }
}

// ---------------- K1: fused init + normalize + sorts ----------------
__global__ void prepK(const float* __restrict__ emb, const float* __restrict__ au,
                      const float* __restrict__ tg) {
    __shared__ float s[N];
    __shared__ float thSh;
    int tid = threadIdx.x;  // 1024
    if (blockIdx.x < 128) {
        int row = blockIdx.x * 32 + (tid >> 5);
        int lane = tid & 31;
        const float4* p = (const float4*)(emb + (size_t)row * D);
        float4 v = p[lane];
        float ss = v.x * v.x + v.y * v.y + v.z * v.z + v.w * v.w;
#pragma unroll
        for (int st = 16; st > 0; st >>= 1) ss += __shfl_xor_sync(0xffffffffu, ss, st);
        float inv = 1.0f / fmaxf(sqrtf(ss), 1e-12f);
        float4 o;
        o.x = v.x * inv; o.y = v.y * inv; o.z = v.z * inv; o.w = v.w * inv;
        ((float4*)(g_en + (size_t)row * D))[lane] = o;
        return;
    }
    if (blockIdx.x == 128) {
        // init accumulators + sort aleatoric uncertainty -> median -> low mask
        for (int x = tid; x < N; x += 1024) {
            g_rowMinPos[x] = 0xFFFFFFFFu;
            g_rowMaxNeg[x] = 0u;
        }
        for (int i = tid; i < N; i += 1024) s[i] = au[i];
        __syncthreads();
        bitonicSort(s);
        if (tid == 0) thSh = 0.5f * s[2047] + 0.5f * s[2048];
        __syncthreads();
        float th = thSh;
        for (int i = tid; i < N; i += 1024) g_low[i] = (au[i] < th) ? 1 : 0;
        return;
    }
    // block 129: sort targets
    for (int i = tid; i < N; i += 1024) s[i] = tg[i];
    __syncthreads();
    bitonicSort(s);
    for (int i = tid; i < N; i += 1024) g_tsorted[i] = s[i];
}

// block-wide reduce-sum of unsigned with broadcast to all threads
__device__ unsigned blockSumBcast(unsigned v, unsigned* warpS) {
    int tid = threadIdx.x, lane = tid & 31, wid = tid >> 5;
#pragma unroll
    for (int s = 16; s > 0; s >>= 1) v += __shfl_xor_sync(0xffffffffu, v, s);
    __syncthreads();
    if (lane == 0) warpS[wid] = v;
    __syncthreads();
    if (wid == 0) {
        unsigned w = warpS[lane];
#pragma unroll
        for (int s = 16; s > 0; s >>= 1) w += __shfl_xor_sync(0xffffffffu, w, s);
        if (lane == 0) warpS[0] = w;
    }
    __syncthreads();
    unsigned r = warpS[0];
    __syncthreads();
    return r;
}

// count pairs (i<j in sorted order) with fl(ts[j] - ts[i]) <= x   (x >= 0)
__device__ unsigned cntLE(const float* ts, float x, unsigned* warpS) {
    int tid = threadIdx.x;
    unsigned c = 0;
    for (int i = tid; i < N; i += 1024) {
        float ti = ts[i];
        int lo = i, hi = N - 1;
        // pred(j): ts[j] - ti <= x ; monotone non-increasing in j; pred(i) true
#pragma unroll 1
        while (lo < hi) {
            int mid = (lo + hi + 1) >> 1;
            if (ts[mid] - ti <= x) lo = mid; else hi = mid - 1;
        }
        c += (unsigned)(lo - i);
    }
    return blockSumBcast(c, warpS);
}

// ---------------- K2: exact quantile order statistics via bit-pattern binary search ----------------
__global__ void selectK() {
    __shared__ float ts[N];
    __shared__ unsigned warpS[32];
    int tid = threadIdx.x;  // 1024
    for (int i = tid; i < N; i += 1024) ts[i] = g_tsorted[i];
    __syncthreads();

    // zero pairs (diff == 0)
    unsigned z = cntLE(ts, 0.0f, warpS);

    // replicate jax fp32 rank arithmetic
    unsigned long long n = 16773120ull - 2ull * (unsigned long long)z;
    float nf = (float)(n - 1ull);
    float pos = 0.2f * nf;
    float lof = floorf(pos);
    float frac = pos - lof;
    unsigned flatLo = (unsigned)lof;
    unsigned flatHi = (frac > 0.0f) ? flatLo + 1u : flatLo;
    // flat (duplicated) rank -> unordered-pair rank
    unsigned k = (blockIdx.x == 0) ? (flatLo >> 1) : (flatHi >> 1);
    unsigned target = k + 1u + z;   // want minimal v with cntLE(v) >= target

    unsigned lov = 0u, hiv = 0x7F7FFFFFu;
#pragma unroll 1
    while (lov < hiv) {
        unsigned mid = (lov + hiv) >> 1;
        unsigned c = cntLE(ts, __uint_as_float(mid), warpS);
        if (c >= target) hiv = mid; else lov = mid + 1u;
    }
    if (tid == 0) {
        if (blockIdx.x == 0) { g_vloBits = hiv; g_frac = frac; }
        else g_vhiBits = hiv;
    }
}

// ---------------- K3: symmetric fp32x2 GEMM + fused masked row/col reductions ----------------
__global__ __launch_bounds__(256, 1) void gemmMaskK(const float* __restrict__ t) {
    __shared__ __align__(16) float2 As2[16][128];
    __shared__ __align__(16) float2 Bs2[16][128];
    __shared__ unsigned sColMin[8][128];
    __shared__ unsigned sColMax[8][128];

    int tid = threadIdx.x;
    // triangular block mapping: bi <= bj over 32x32 tiles (528 blocks)
    int b = blockIdx.x;
    int bi = 0;
    while (b >= 32 - bi) { b -= 32 - bi; bi++; }
    int bj = bi + b;
    int ri = bi * 128, rj = bj * 128;

    int r0 = (tid >> 4) * 4;
    int c0 = (tid & 15) * 4;

    unsigned long long acc[8][8];
#pragma unroll
    for (int r = 0; r < 8; r++)
#pragma unroll
        for (int c = 0; c < 8; c++) acc[r][c] = 0ull;

    int lr = tid >> 1, lh = tid & 1;
    for (int kc = 0; kc < 4; kc++) {
        const float4* pa = (const float4*)(g_en + (size_t)(ri + lr) * D + kc * 32 + lh * 16);
        const float4* pb = (const float4*)(g_en + (size_t)(rj + lr) * D + kc * 32 + lh * 16);
        float4 a0 = pa[0], a1 = pa[1], a2 = pa[2], a3 = pa[3];
        float4 b0 = pb[0], b1 = pb[1], b2 = pb[2], b3 = pb[3];
        if (kc) __syncthreads();
        int kb = lh * 8;
        As2[kb + 0][lr] = make_float2(a0.x, a0.y);
        As2[kb + 1][lr] = make_float2(a0.z, a0.w);
        As2[kb + 2][lr] = make_float2(a1.x, a1.y);
        As2[kb + 3][lr] = make_float2(a1.z, a1.w);
        As2[kb + 4][lr] = make_float2(a2.x, a2.y);
        As2[kb + 5][lr] = make_float2(a2.z, a2.w);
        As2[kb + 6][lr] = make_float2(a3.x, a3.y);
        As2[kb + 7][lr] = make_float2(a3.z, a3.w);
        Bs2[kb + 0][lr] = make_float2(b0.x, b0.y);
        Bs2[kb + 1][lr] = make_float2(b0.z, b0.w);
        Bs2[kb + 2][lr] = make_float2(b1.x, b1.y);
        Bs2[kb + 3][lr] = make_float2(b1.z, b1.w);
        Bs2[kb + 4][lr] = make_float2(b2.x, b2.y);
        Bs2[kb + 5][lr] = make_float2(b2.z, b2.w);
        Bs2[kb + 6][lr] = make_float2(b3.x, b3.y);
        Bs2[kb + 7][lr] = make_float2(b3.z, b3.w);
        __syncthreads();
#pragma unroll
        for (int k2 = 0; k2 < 16; k2++) {
            ulonglong2 A0 = *(const ulonglong2*)&As2[k2][r0];
            ulonglong2 A1 = *(const ulonglong2*)&As2[k2][r0 + 2];
            ulonglong2 A2 = *(const ulonglong2*)&As2[k2][64 + r0];
            ulonglong2 A3 = *(const ulonglong2*)&As2[k2][64 + r0 + 2];
            ulonglong2 B0 = *(const ulonglong2*)&Bs2[k2][c0];
            ulonglong2 B1 = *(const ulonglong2*)&Bs2[k2][c0 + 2];
            ulonglong2 B2 = *(const ulonglong2*)&Bs2[k2][64 + c0];
            ulonglong2 B3 = *(const ulonglong2*)&Bs2[k2][64 + c0 + 2];
            unsigned long long av[8] = {A0.x, A0.y, A1.x, A1.y, A2.x, A2.y, A3.x, A3.y};
            unsigned long long bv[8] = {B0.x, B0.y, B1.x, B1.y, B2.x, B2.y, B3.x, B3.y};
#pragma unroll
            for (int r = 0; r < 8; r++)
#pragma unroll
                for (int c = 0; c < 8; c++)
                    asm("fma.rn.f32x2 %0, %1, %2, %0;"
                        : "+l"(acc[r][c]) : "l"(av[r]), "l"(bv[c]));
        }
    }

    // unpack packed partial sums
    float dot[8][8];
#pragma unroll
    for (int r = 0; r < 8; r++)
#pragma unroll
        for (int c = 0; c < 8; c++) {
            float lo = __uint_as_float((unsigned)(acc[r][c] & 0xFFFFFFFFull));
            float hi = __uint_as_float((unsigned)(acc[r][c] >> 32));
            dot[r][c] = lo + hi;
        }

    // act threshold (computed inline; deterministic)
    float flo = __uint_as_float(g_vloBits);
    float fhi = __uint_as_float(g_vhiBits);
    float fr = g_frac;
    float actT = __fadd_rn(__fmul_rn(flo, 1.0f - fr), __fmul_rn(fhi, fr));

    // ---- fused epilogue: masked min/max for BOTH row anchors and col anchors ----
    int rows[8], cols[8];
#pragma unroll
    for (int u = 0; u < 4; u++) {
        rows[u] = ri + r0 + u;
        rows[4 + u] = ri + 64 + r0 + u;
        cols[u] = rj + c0 + u;
        cols[4 + u] = rj + 64 + c0 + u;
    }
    float ti[8], tj[8];
    int li[8], lj[8];
#pragma unroll
    for (int u = 0; u < 8; u++) {
        ti[u] = t[rows[u]];
        tj[u] = t[cols[u]];
        li[u] = g_low[rows[u]];
        lj[u] = g_low[cols[u]];
    }
    float pMin[8], nMax[8], cMin[8], cMax[8];
#pragma unroll
    for (int u = 0; u < 8; u++) {
        pMin[u] = 3.402823466e38f; nMax[u] = -3.402823466e38f;
        cMin[u] = 3.402823466e38f; cMax[u] = -3.402823466e38f;
    }
#pragma unroll
    for (int r = 0; r < 8; r++) {
#pragma unroll
        for (int c = 0; c < 8; c++) {
            float ad = fabsf(ti[r] - tj[c]);
            if (ad < actT) {
                float dv = dot[r][c];
                bool neq = rows[r] != cols[c];
                if (lj[c]) { if (neq) pMin[r] = fminf(pMin[r], dv); }
                else nMax[r] = fmaxf(nMax[r], dv);
                if (li[r]) { if (neq) cMin[c] = fminf(cMin[c], dv); }
                else cMax[c] = fmaxf(cMax[c], dv);
            }
        }
    }
    // row side: reduce across 16-lane groups sharing the same rows
#pragma unroll
    for (int s = 8; s > 0; s >>= 1) {
#pragma unroll
        for (int r = 0; r < 8; r++) {
            pMin[r] = fminf(pMin[r], __shfl_down_sync(0xffffffffu, pMin[r], s, 16));
            nMax[r] = fmaxf(nMax[r], __shfl_down_sync(0xffffffffu, nMax[r], s, 16));
        }
    }
    if ((tid & 15) == 0) {
#pragma unroll
        for (int r = 0; r < 8; r++) {
            if (pMin[r] < 3.0e38f) atomicMin(&g_rowMinPos[rows[r]], encodeF(pMin[r]));
            if (nMax[r] > -3.0e38f) atomicMax(&g_rowMaxNeg[rows[r]], encodeF(nMax[r]));
        }
    }
    // col side: combine lane pairs (l, l^16), stage per-warp partials, then flush
    unsigned eMin[8], eMax[8];
#pragma unroll
    for (int u = 0; u < 8; u++) {
        eMin[u] = encodeF(cMin[u]);
        eMax[u] = encodeF(cMax[u]);
        eMin[u] = min(eMin[u], __shfl_xor_sync(0xffffffffu, eMin[u], 16));
        eMax[u] = max(eMax[u], __shfl_xor_sync(0xffffffffu, eMax[u], 16));
    }
    int wrp = tid >> 5;
    if ((tid & 31) < 16) {
#pragma unroll
        for (int u = 0; u < 4; u++) {
            sColMin[wrp][c0 + u] = eMin[u];
            sColMin[wrp][64 + c0 + u] = eMin[4 + u];
            sColMax[wrp][c0 + u] = eMax[u];
            sColMax[wrp][64 + c0 + u] = eMax[4 + u];
        }
    }
    __syncthreads();
    if (tid < 128) {
        unsigned v = sColMin[0][tid];
#pragma unroll
        for (int w = 1; w < 8; w++) v = min(v, sColMin[w][tid]);
        if (v < 0xFF000000u) atomicMin(&g_rowMinPos[rj + tid], v);
    } else if (tid < 256) {
        int c = tid - 128;
        unsigned v = sColMax[0][c];
#pragma unroll
        for (int w = 1; w < 8; w++) v = max(v, sColMax[w][c]);
        if (v > 0x01000000u) atomicMax(&g_rowMaxNeg[rj + c], v);
    }
}

// ---------------- K4: per-anchor loss + mean ----------------
__global__ void finalK(float* __restrict__ out, int out_size) {
    __shared__ float sSum[32];
    __shared__ unsigned sCnt[32];
    int tid = threadIdx.x;  // 1024
    int lane = tid & 31, wid = tid >> 5;
    float sum = 0.0f;
    unsigned cnt = 0u;
    for (int i = tid; i < N; i += 1024) {
        if (!g_low[i]) continue;
        unsigned ep = g_rowMinPos[i];
        if (ep == 0xFFFFFFFFu) continue;  // no positive
        unsigned en = g_rowMaxNeg[i];
        if (en == 0u) continue;           // no negative
        float minDot = decodeF(ep);
        float maxDot = decodeF(en);
        float hp = sqrtf(fmaxf(2.0f - 2.0f * minDot, 1e-12f));
        float hn = sqrtf(fmaxf(2.0f - 2.0f * maxDot, 1e-12f));
        float tl = hp - hn + 0.5f;
        if (tl < 0.0f) tl = 0.0f;
        sum += tl;
        cnt++;
    }
#pragma unroll
    for (int s = 16; s > 0; s >>= 1) {
        sum += __shfl_down_sync(0xffffffffu, sum, s);
        cnt += __shfl_down_sync(0xffffffffu, cnt, s);
    }
    if (lane == 0) { sSum[wid] = sum; sCnt[wid] = cnt; }
    __syncthreads();
    if (wid == 0) {
        float s2 = sSum[lane];
        unsigned c2 = sCnt[lane];
#pragma unroll
        for (int s = 16; s > 0; s >>= 1) {
            s2 += __shfl_down_sync(0xffffffffu, s2, s);
            c2 += __shfl_down_sync(0xffffffffu, c2, s);
        }
        if (lane == 0) out[0] = s2 / (float)(c2 > 0u ? c2 : 1u);
    }
    for (int i = tid; i < out_size; i += 1024)
        if (i > 0) out[i] = 0.0f;
}

// ---------------- launch ----------------
extern "C" void kernel_launch(void* const* d_in, const int* in_sizes, int n_in,
                              void* d_out, int out_size) {
    const float* emb = (const float*)d_in[0];
    const float* tg = (const float*)d_in[1];
    const float* au = (const float*)d_in[2];
    float* out = (float*)d_out;

    prepK<<<130, 1024>>>(emb, au, tg);
    selectK<<<2, 1024>>>();
    gemmMaskK<<<528, 256>>>(tg);
    finalK<<<1, 1024>>>(out, out_size);
}